// round 16
// baseline (speedup 1.0000x reference)
#include <cuda_runtime.h>
#include <cuda_fp16.h>
#include <cstdint>

#define N_NODES 100000
#define IN_DIM  128
#define OUT_DIM 32
#define HEADS   8
#define HF      256   // HEADS*OUT_DIM
#define NEG_SLOPE 0.2f
#define MAX_SLOTS 1800000   // >= E + N_NODES
#define SCAN_NB  ((N_NODES + 1023) / 1024)   // 98 blocks — single wave, co-resident

#define GBM 256
#define GBN 64
#define GBK 64
#define M_TILES ((N_NODES + GBM - 1) / GBM)   // 391
#define N_TILES (HF / GBN)                    // 4
#define NTILES  (M_TILES * N_TILES)           // 1564
#define GEMM_GRID 296     // 2/SM persistent wave; 296 % 4 == 0 -> n-tile fixed per block
#define A_STAGE_B (256 * 128)   // 32 KB per A stage
#define B_CHUNK_B (64 * 128)    // 8 KB per B k-chunk (2 chunks, loaded once)
#define GEMM_SMEM (2 * A_STAGE_B + 2 * B_CHUNK_B)   // 81920

// ---------------- scratch (static device globals; no allocation) ----------------
__device__ __align__(256) __half g_hh[(size_t)N_NODES * HF]; // fp16 h [N, H*F]
__device__ float g_asrc[N_NODES * HEADS];
__device__ float g_adst[N_NODES * HEADS];
__device__ int   g_is64;
__device__ __align__(256) __half g_Ah[(size_t)N_NODES * IN_DIM];  // fp16 X
__device__ __align__(256) __half g_Bth[HF * IN_DIM];              // W^T fp16 [n][k]
// counting sort by destination
__device__ int g_cnt[N_NODES];
__device__ int g_off[N_NODES + 1];
__device__ int g_cur[N_NODES];
__device__ int g_bsum[128];
__device__ int g_boff[128];
__device__ int g_ticket;
__device__ int g_flag;
__device__ int g_ssrc[MAX_SLOTS];

__device__ __forceinline__ void load_edge(const void* EI, long long e, int E,
                                          int is64, int& s, int& d) {
    if (is64) {
        const long long* p = (const long long*)EI;
        s = (int)p[e]; d = (int)p[e + E];
    } else {
        const int* p = (const int*)EI;
        s = p[e]; d = p[e + E];
    }
}

// ---------------- K0: dtype probe + per-replay state re-init ------------------
__global__ void init_kernel(const void* EI) {
    int i = blockIdx.x * blockDim.x + threadIdx.x;
    if (i == 0) {
        const long long* p = (const long long*)EI;
        int is64 = 1;
        #pragma unroll
        for (int k = 0; k < 64; k++) {
            long long v = p[k];
            if (v < 0 || v >= N_NODES) is64 = 0;
        }
        g_is64 = is64;
        g_ticket = 0;
        g_flag = 0;
    }
    if (i < N_NODES) g_cnt[i] = 1;   // bake the self loop
}

// ---------------- K1: X -> fp16 + W fp16 transpose + degree histogram --------
__global__ void prep_kernel(const float* __restrict__ X,
                            const float* __restrict__ W,
                            const void* __restrict__ EI, int E) {
    int i = blockIdx.x * blockDim.x + threadIdx.x;
    if (i < N_NODES * IN_DIM / 4) {
        float4 v = ((const float4*)X)[i];
        ((__half2*)g_Ah)[2 * i]     = __floats2half2_rn(v.x, v.y);
        ((__half2*)g_Ah)[2 * i + 1] = __floats2half2_rn(v.z, v.w);
    }
    if (i < IN_DIM * HF) {           // W fp16 + transpose: [k][n] -> [n][k]
        int k = i >> 8;
        int n = i & 255;
        g_Bth[n * IN_DIM + k] = __float2half_rn(W[i]);
    }
    if (i < E) {                     // degree histogram (dst half of EI)
        int d;
        if (g_is64) d = (int)((const long long*)EI)[i + E];
        else        d = ((const int*)EI)[i + E];
        atomicAdd(&g_cnt[d], 1);
    }
}

// ---------------- K2: single-launch fused hierarchical exclusive scan --------
__device__ __forceinline__ int block_scan_excl(int x, int* total) {
    int lane = threadIdx.x & 31, w = threadIdx.x >> 5;
    int v = x;
    #pragma unroll
    for (int o = 1; o < 32; o <<= 1) {
        int t = __shfl_up_sync(0xffffffffu, v, o);
        if (lane >= o) v += t;
    }
    __shared__ int ws[32];
    if (lane == 31) ws[w] = v;
    __syncthreads();
    if (w == 0) {
        int u = ws[lane];
        #pragma unroll
        for (int o = 1; o < 32; o <<= 1) {
            int t = __shfl_up_sync(0xffffffffu, u, o);
            if (lane >= o) u += t;
        }
        ws[lane] = u;
    }
    __syncthreads();
    int incl = v + (w > 0 ? ws[w - 1] : 0);
    *total = ws[31];
    return incl - x;
}

__global__ void scan_kernel(int E) {
    const int tid = threadIdx.x;
    const int bid = blockIdx.x;
    int i = bid * 1024 + tid;
    int x = (i < N_NODES) ? g_cnt[i] : 0;
    int total;
    int ex = block_scan_excl(x, &total);

    __shared__ int is_last;
    if (tid == 0) {
        g_bsum[bid] = total;
        __threadfence();
        int t = atomicAdd(&g_ticket, 1);
        is_last = (t == SCAN_NB - 1);
    }
    __syncthreads();

    if (is_last) {
        int b = tid;
        int x2 = (b < SCAN_NB) ? g_bsum[b] : 0;
        int tot2;
        int ex2 = block_scan_excl(x2, &tot2);
        if (b < SCAN_NB) g_boff[b] = ex2;
        if (tid == 0) {
            g_off[N_NODES] = E + N_NODES;
            __threadfence();
            atomicExch(&g_flag, 1);
        }
    }

    if (tid == 0) {
        while (atomicAdd(&g_flag, 0) == 0) { }
    }
    __syncthreads();

    if (i < N_NODES) {
        int off = ex + g_boff[bid];
        g_off[i] = off;
        g_cur[i] = off;
    }
}

// ---------------- K3: persistent fp16 GEMM, m32xn64 warptiles ----------------
// GBM=256, 8 warps each own m32 x n64: A read once (no m-redundancy), B
// redundancy halved per row -> 96 KB smem traffic per 256 rows (was 160).
// 296 % 4 == 0 -> fixed n0 per block; 16 KB B slab loaded once at prologue.
__device__ __forceinline__ void ldsm_x4(uint32_t& r0, uint32_t& r1,
                                        uint32_t& r2, uint32_t& r3, uint32_t addr) {
    asm volatile("ldmatrix.sync.aligned.m8n8.x4.shared.b16 {%0,%1,%2,%3}, [%4];\n"
                 : "=r"(r0), "=r"(r1), "=r"(r2), "=r"(r3) : "r"(addr));
}

__device__ __forceinline__ void mma_fp16(float c[4], const uint32_t a[4],
                                         const uint32_t b[2]) {
    asm volatile(
        "mma.sync.aligned.m16n8k16.row.col.f32.f16.f16.f32 "
        "{%0,%1,%2,%3},{%4,%5,%6,%7},{%8,%9},{%0,%1,%2,%3};\n"
        : "+f"(c[0]), "+f"(c[1]), "+f"(c[2]), "+f"(c[3])
        : "r"(a[0]), "r"(a[1]), "r"(a[2]), "r"(a[3]), "r"(b[0]), "r"(b[1]));
}

__device__ __forceinline__ void cp16(uint32_t dst, const void* src, int srcsize) {
    asm volatile("cp.async.cg.shared.global [%0], [%1], 16, %2;\n"
                 :: "r"(dst), "l"(src), "r"(srcsize) : "memory");
}
__device__ __forceinline__ void cp_commit() {
    asm volatile("cp.async.commit_group;\n" ::: "memory");
}
template <int N>
__device__ __forceinline__ void cp_wait() {
    asm volatile("cp.async.wait_group %0;\n" :: "n"(N) : "memory");
}

__global__ __launch_bounds__(256, 2)
void gemm_fp16_kernel(const float* __restrict__ att_src,
                      const float* __restrict__ att_dst,
                      const void* __restrict__ EI, int E) {
    extern __shared__ __align__(16) char dynsmem[];

    const int tid  = threadIdx.x;
    const int lane = tid & 31;
    const int warp = tid >> 5;
    const int wm = warp * 32;               // warp owns rows [wm, wm+32)
    const int bid = blockIdx.x;
    const int n0  = (bid & 3) * GBN;        // fixed for the whole block

    const uint32_t baseA = (uint32_t)__cvta_generic_to_shared(dynsmem);
    const uint32_t baseB = baseA + 2 * A_STAGE_B;

    const int ntiles = (NTILES - bid + GEMM_GRID - 1) / GEMM_GRID;
    const int P = 2 * ntiles;

    auto issueA = [&](int p) {
        const int T = bid + (p >> 1) * GEMM_GRID;
        const int row0 = (T >> 2) * GBM;
        const int stage = p & 1;
        const int kk = (p & 1) * GBK;
        #pragma unroll
        for (int j = 0; j < 8; j++) {
            int slot = tid + j * 256;        // 0..2047
            int r  = slot >> 3;              // 0..255
            int cc = slot & 7;
            int gr = row0 + r;
            const void* src = &g_Ah[(size_t)min(gr, N_NODES - 1) * IN_DIM + kk + cc * 8];
            uint32_t dst = baseA + stage * A_STAGE_B + r * 128 + (cc ^ (r & 7)) * 16;
            cp16(dst, src, (gr < N_NODES) ? 16 : 0);
        }
        cp_commit();
    };

    // ---- prologue: B slab once (group 0) + first two A chunks ----
    {
        #pragma unroll
        for (int j = 0; j < 4; j++) {
            int slot = tid + j * 256;        // 0..1023
            int c  = slot >> 9;              // k-chunk 0/1
            int s2 = slot & 511;
            int r  = s2 >> 3;
            int cc = s2 & 7;
            const void* src = &g_Bth[(size_t)(n0 + r) * IN_DIM + c * GBK + cc * 8];
            uint32_t dst = baseB + c * B_CHUNK_B + r * 128 + (cc ^ (r & 7)) * 16;
            cp16(dst, src, 16);
        }
        cp_commit();
    }
    issueA(0);
    issueA(1);

    float acc[2][8][4];
    #pragma unroll
    for (int i = 0; i < 2; i++)
        #pragma unroll
        for (int j = 0; j < 8; j++)
            #pragma unroll
            for (int e = 0; e < 4; e++) acc[i][j][e] = 0.f;

    // ---- fused scatter: hides the prologue fill latency ----
    {
        const int is64 = g_is64;
        const int nthreads = GEMM_GRID * 256;
        int e = bid * 256 + tid;
        const int total = E + N_NODES;
        for (; e < total; e += nthreads) {
            int s, d;
            if (e < E) load_edge(EI, e, E, is64, s, d);
            else       s = d = e - E;
            int pos = atomicAdd(&g_cur[d], 1);
            g_ssrc[pos] = s;
        }
    }

    #pragma unroll 1
    for (int p = 0; p < P; p++) {
        if (p < P - 1) cp_wait<1>();
        else           cp_wait<0>();
        __syncthreads();

        const uint32_t aOff = baseA + (p & 1) * A_STAGE_B;
        const uint32_t bOff = baseB + (p & 1) * B_CHUNK_B;
        #pragma unroll
        for (int k0 = 0; k0 < GBK; k0 += 16) {
            uint32_t a[2][4];
            #pragma unroll
            for (int i = 0; i < 2; i++) {
                int r = wm + 16 * i + (lane & 15);
                int cc = (k0 >> 3) + ((lane >> 4) & 1);
                ldsm_x4(a[i][0], a[i][1], a[i][2], a[i][3],
                        aOff + r * 128 + ((cc ^ (r & 7)) * 16));
            }
            uint32_t b[8][2];
            #pragma unroll
            for (int jj = 0; jj < 4; jj++) {   // n16 blocks 0..3 over n=64
                int r = jj * 16 + (lane & 7) + ((lane & 16) ? 8 : 0);
                int cc = (k0 >> 3) + ((lane >> 3) & 1);
                uint32_t r0, r1, r2, r3;
                ldsm_x4(r0, r1, r2, r3, bOff + r * 128 + ((cc ^ (r & 7)) * 16));
                b[2 * jj][0] = r0; b[2 * jj][1] = r1;
                b[2 * jj + 1][0] = r2; b[2 * jj + 1][1] = r3;
            }
            #pragma unroll
            for (int i = 0; i < 2; i++)
                #pragma unroll
                for (int j = 0; j < 8; j++)
                    mma_fp16(acc[i][j], a[i], b[j]);
        }
        __syncthreads();          // stage reads done; safe to refill
        if (p + 2 < P) issueA(p + 2);

        if (p & 1) {
            // ---- tile epilogue: store h (fp16) + logits for the 2 heads ----
            const int T = bid + (p >> 1) * GEMM_GRID;
            const int row0 = (T >> 2) * GBM;
            const int g   = lane >> 2;
            const int tig = lane & 3;
            const int head0 = n0 >> 5;      // warp covers heads head0, head0+1

            // store h
            #pragma unroll
            for (int i = 0; i < 2; i++) {
                int row1 = row0 + wm + 16 * i + g;
                int row2 = row1 + 8;
                #pragma unroll
                for (int j = 0; j < 8; j++) {
                    int colg = n0 + j * 8 + 2 * tig;
                    if (row1 < N_NODES)
                        *(__half2*)&g_hh[(size_t)row1 * HF + colg] =
                            __floats2half2_rn(acc[i][j][0], acc[i][j][1]);
                    if (row2 < N_NODES)
                        *(__half2*)&g_hh[(size_t)row2 * HF + colg] =
                            __floats2half2_rn(acc[i][j][2], acc[i][j][3]);
                }
            }
            // logits, one head at a time
            #pragma unroll
            for (int hh = 0; hh < 2; hh++) {
                float as_v[4][2], ad_v[4][2];
                #pragma unroll
                for (int j = 0; j < 4; j++) {
                    int col = j * 8 + 2 * tig;
                    as_v[j][0] = att_src[(head0 + hh) * 32 + col];
                    as_v[j][1] = att_src[(head0 + hh) * 32 + col + 1];
                    ad_v[j][0] = att_dst[(head0 + hh) * 32 + col];
                    ad_v[j][1] = att_dst[(head0 + hh) * 32 + col + 1];
                }
                float ps[4] = {0.f, 0.f, 0.f, 0.f}, pd[4] = {0.f, 0.f, 0.f, 0.f};
                #pragma unroll
                for (int i = 0; i < 2; i++)
                    #pragma unroll
                    for (int j = 0; j < 4; j++) {
                        const float* c = acc[i][hh * 4 + j];
                        ps[2 * i]     += c[0] * as_v[j][0] + c[1] * as_v[j][1];
                        ps[2 * i + 1] += c[2] * as_v[j][0] + c[3] * as_v[j][1];
                        pd[2 * i]     += c[0] * ad_v[j][0] + c[1] * ad_v[j][1];
                        pd[2 * i + 1] += c[2] * ad_v[j][0] + c[3] * ad_v[j][1];
                    }
                #pragma unroll
                for (int s = 0; s < 4; s++) {
                    ps[s] += __shfl_xor_sync(0xffffffffu, ps[s], 1);
                    ps[s] += __shfl_xor_sync(0xffffffffu, ps[s], 2);
                    pd[s] += __shfl_xor_sync(0xffffffffu, pd[s], 1);
                    pd[s] += __shfl_xor_sync(0xffffffffu, pd[s], 2);
                }
                if (tig == 0) {
                    #pragma unroll
                    for (int s = 0; s < 4; s++) {
                        int row = row0 + wm + 16 * (s >> 1) + 8 * (s & 1) + g;
                        if (row < N_NODES) {
                            g_asrc[row * HEADS + head0 + hh] = ps[s];
                            g_adst[row * HEADS + head0 + hh] = pd[s];
                        }
                    }
                }
            }
            // reset accumulators for the next tile
            #pragma unroll
            for (int i = 0; i < 2; i++)
                #pragma unroll
                for (int j = 0; j < 8; j++)
                    #pragma unroll
                    for (int e2 = 0; e2 < 4; e2++) acc[i][j][e2] = 0.f;
        }
    }
}

// ---------------- K4: fused softmax + aggregation (warp per destination) ------
__global__ void agg2_kernel(const float* __restrict__ bias,
                            float* __restrict__ out) {
    int wid  = (blockIdx.x * blockDim.x + threadIdx.x) >> 5;
    int lane = threadIdx.x & 31;
    if (wid >= N_NODES) return;
    const int d = wid;
    const int beg = g_off[d], end = g_off[d + 1];
    const int hd = lane >> 2;

    float adv = (lane < HEADS) ? g_adst[d * HEADS + lane] : 0.f;
    float num[8] = {0.f, 0.f, 0.f, 0.f, 0.f, 0.f, 0.f, 0.f};
    float den = 0.f;

    auto weight = [&](int s) -> float {
        float w = 0.f;
        if (lane < HEADS) {
            float x = __ldg(&g_asrc[s * HEADS + lane]) + adv;
            x = (x > 0.f) ? x : NEG_SLOPE * x;
            w = __expf(x);
            den += w;
        }
        return w;
    };
    auto accum = [&](uint4 v, float w) {
        float wh = __shfl_sync(0xffffffffu, w, hd);
        const __half2* hp = (const __half2*)&v;
        #pragma unroll
        for (int k = 0; k < 4; k++) {
            float2 f = __half22float2(hp[k]);
            num[2 * k]     += wh * f.x;
            num[2 * k + 1] += wh * f.y;
        }
    };

    int i = beg;
    for (; i + 4 <= end; i += 4) {
        int s0 = __ldg(&g_ssrc[i]);
        int s1 = __ldg(&g_ssrc[i + 1]);
        int s2 = __ldg(&g_ssrc[i + 2]);
        int s3 = __ldg(&g_ssrc[i + 3]);
        uint4 v0 = __ldg((const uint4*)&g_hh[(size_t)s0 * HF + lane * 8]);
        uint4 v1 = __ldg((const uint4*)&g_hh[(size_t)s1 * HF + lane * 8]);
        uint4 v2 = __ldg((const uint4*)&g_hh[(size_t)s2 * HF + lane * 8]);
        uint4 v3 = __ldg((const uint4*)&g_hh[(size_t)s3 * HF + lane * 8]);
        float w0 = weight(s0);
        float w1 = weight(s1);
        float w2 = weight(s2);
        float w3 = weight(s3);
        accum(v0, w0);
        accum(v1, w1);
        accum(v2, w2);
        accum(v3, w3);
    }
    for (; i < end; i++) {
        int s0 = __ldg(&g_ssrc[i]);
        uint4 v0 = __ldg((const uint4*)&g_hh[(size_t)s0 * HF + lane * 8]);
        accum(v0, weight(s0));
    }

    float dh = __shfl_sync(0xffffffffu, den, hd);
    float inv = 1.0f / (dh + 1e-16f);
    #pragma unroll
    for (int j = 0; j < 8; j++) {
        float c = num[j] * inv;
        c += __shfl_xor_sync(0xffffffffu, c, 4);
        c += __shfl_xor_sync(0xffffffffu, c, 8);
        c += __shfl_xor_sync(0xffffffffu, c, 16);
        num[j] = c;
    }
    if (lane < 4) {
        float4 b0 = ((const float4*)bias)[lane * 2];
        float4 b1 = ((const float4*)bias)[lane * 2 + 1];
        float4 o0 = make_float4(num[0] * 0.125f + b0.x, num[1] * 0.125f + b0.y,
                                num[2] * 0.125f + b0.z, num[3] * 0.125f + b0.w);
        float4 o1 = make_float4(num[4] * 0.125f + b1.x, num[5] * 0.125f + b1.y,
                                num[6] * 0.125f + b1.z, num[7] * 0.125f + b1.w);
        ((float4*)&out[d * OUT_DIM])[lane * 2]     = o0;
        ((float4*)&out[d * OUT_DIM])[lane * 2 + 1] = o1;
    }
}

// ---------------- launch ----------------
extern "C" void kernel_launch(void* const* d_in, const int* in_sizes, int n_in,
                              void* d_out, int out_size) {
    const float* X       = (const float*)d_in[0];
    const void*  EI      = d_in[1];
    const float* W       = (const float*)d_in[2];
    const float* att_src = (const float*)d_in[3];
    const float* att_dst = (const float*)d_in[4];
    const float* bias    = (const float*)d_in[5];
    float* out = (float*)d_out;

    int E = in_sizes[1] / 2;

    init_kernel<<<(N_NODES + 255) / 256, 256>>>(EI);
    prep_kernel<<<(N_NODES * IN_DIM / 4 + 255) / 256, 256>>>(X, W, EI, E);
    scan_kernel<<<SCAN_NB, 1024>>>(E);

    cudaFuncSetAttribute(gemm_fp16_kernel,
                         cudaFuncAttributeMaxDynamicSharedMemorySize, GEMM_SMEM);
    (void)cudaGetLastError();
    gemm_fp16_kernel<<<GEMM_GRID, 256, GEMM_SMEM>>>(att_src, att_dst, EI, E);

    agg2_kernel<<<(N_NODES * 32 + 255) / 256, 256>>>(bias, out);
}

// round 17
// speedup vs baseline: 1.0336x; 1.0336x over previous
#include <cuda_runtime.h>
#include <cuda_fp16.h>
#include <cstdint>

#define N_NODES 100000
#define IN_DIM  128
#define OUT_DIM 32
#define HEADS   8
#define HF      256   // HEADS*OUT_DIM
#define NEG_SLOPE 0.2f
#define MAX_SLOTS 1800000   // >= E + N_NODES
#define SCAN_NB  ((N_NODES + 1023) / 1024)   // 98 blocks — single wave, co-resident

#define GBM 128
#define GBN 64
#define GBK 64
#define M_TILES ((N_NODES + GBM - 1) / GBM)   // 782
#define N_TILES (HF / GBN)                    // 4
#define NTILES  (M_TILES * N_TILES)           // 3128
#define GEMM_GRID 444     // 3/SM persistent wave; 444 % 4 == 0 -> n-tile fixed per block
#define A_STAGE_B (128 * 128)   // 16 KB per A stage
#define B_CHUNK_B (64 * 128)    // 8 KB per B k-chunk (2 chunks, loaded once)

// ---------------- scratch (static device globals; no allocation) ----------------
__device__ __align__(256) __half g_hh[(size_t)N_NODES * HF]; // fp16 h [N, H*F]
__device__ float g_asrc[N_NODES * HEADS];
__device__ float g_adst[N_NODES * HEADS];
__device__ int   g_is64;
__device__ __align__(256) __half g_Ah[(size_t)N_NODES * IN_DIM];  // fp16 X
__device__ __align__(256) __half g_Bth[HF * IN_DIM];              // W^T fp16 [n][k]
// counting sort by destination
__device__ int g_cnt[N_NODES];
__device__ int g_off[N_NODES + 1];
__device__ int g_cur[N_NODES];
__device__ int g_bsum[128];
__device__ int g_boff[128];
__device__ int g_ticket;
__device__ int g_flag;
__device__ int g_ssrc[MAX_SLOTS];

__device__ __forceinline__ void load_edge(const void* EI, long long e, int E,
                                          int is64, int& s, int& d) {
    if (is64) {
        const long long* p = (const long long*)EI;
        s = (int)p[e]; d = (int)p[e + E];
    } else {
        const int* p = (const int*)EI;
        s = p[e]; d = p[e + E];
    }
}

// ---------------- K0: dtype probe + per-replay state re-init ------------------
__global__ void init_kernel(const void* EI) {
    int i = blockIdx.x * blockDim.x + threadIdx.x;
    if (i == 0) {
        const long long* p = (const long long*)EI;
        int is64 = 1;
        #pragma unroll
        for (int k = 0; k < 64; k++) {
            long long v = p[k];
            if (v < 0 || v >= N_NODES) is64 = 0;
        }
        g_is64 = is64;
        g_ticket = 0;
        g_flag = 0;
    }
    if (i < N_NODES) g_cnt[i] = 1;   // bake the self loop
}

// ---------------- K1: X -> fp16 + W fp16 transpose + degree histogram --------
__global__ void prep_kernel(const float* __restrict__ X,
                            const float* __restrict__ W,
                            const void* __restrict__ EI, int E) {
    int i = blockIdx.x * blockDim.x + threadIdx.x;
    if (i < N_NODES * IN_DIM / 4) {
        float4 v = ((const float4*)X)[i];
        ((__half2*)g_Ah)[2 * i]     = __floats2half2_rn(v.x, v.y);
        ((__half2*)g_Ah)[2 * i + 1] = __floats2half2_rn(v.z, v.w);
    }
    if (i < IN_DIM * HF) {           // W fp16 + transpose: [k][n] -> [n][k]
        int k = i >> 8;
        int n = i & 255;
        g_Bth[n * IN_DIM + k] = __float2half_rn(W[i]);
    }
    if (i < E) {                     // degree histogram (dst half of EI)
        int d;
        if (g_is64) d = (int)((const long long*)EI)[i + E];
        else        d = ((const int*)EI)[i + E];
        atomicAdd(&g_cnt[d], 1);
    }
}

// ---------------- K2: single-launch fused hierarchical exclusive scan --------
__device__ __forceinline__ int block_scan_excl(int x, int* total) {
    int lane = threadIdx.x & 31, w = threadIdx.x >> 5;
    int v = x;
    #pragma unroll
    for (int o = 1; o < 32; o <<= 1) {
        int t = __shfl_up_sync(0xffffffffu, v, o);
        if (lane >= o) v += t;
    }
    __shared__ int ws[32];
    if (lane == 31) ws[w] = v;
    __syncthreads();
    if (w == 0) {
        int u = ws[lane];
        #pragma unroll
        for (int o = 1; o < 32; o <<= 1) {
            int t = __shfl_up_sync(0xffffffffu, u, o);
            if (lane >= o) u += t;
        }
        ws[lane] = u;
    }
    __syncthreads();
    int incl = v + (w > 0 ? ws[w - 1] : 0);
    *total = ws[31];
    return incl - x;
}

__global__ void scan_kernel(int E) {
    const int tid = threadIdx.x;
    const int bid = blockIdx.x;
    int i = bid * 1024 + tid;
    int x = (i < N_NODES) ? g_cnt[i] : 0;
    int total;
    int ex = block_scan_excl(x, &total);

    __shared__ int is_last;
    if (tid == 0) {
        g_bsum[bid] = total;
        __threadfence();
        int t = atomicAdd(&g_ticket, 1);
        is_last = (t == SCAN_NB - 1);
    }
    __syncthreads();

    if (is_last) {
        int b = tid;
        int x2 = (b < SCAN_NB) ? g_bsum[b] : 0;
        int tot2;
        int ex2 = block_scan_excl(x2, &tot2);
        if (b < SCAN_NB) g_boff[b] = ex2;
        if (tid == 0) {
            g_off[N_NODES] = E + N_NODES;
            __threadfence();
            atomicExch(&g_flag, 1);
        }
    }

    if (tid == 0) {
        while (atomicAdd(&g_flag, 0) == 0) { }
    }
    __syncthreads();

    if (i < N_NODES) {
        int off = ex + g_boff[bid];
        g_off[i] = off;
        g_cur[i] = off;
    }
}

// ---------------- K2b: scatter srcs into dst-grouped order (4 edges/thread) --
__global__ void scatter_kernel(const void* __restrict__ EI, int E) {
    int base = blockIdx.x * (blockDim.x * 4) + threadIdx.x;
    int is64 = g_is64;
    int total = E + N_NODES;
    #pragma unroll
    for (int k = 0; k < 4; k++) {
        int e = base + k * blockDim.x;
        if (e < total) {
            int s, d;
            if (e < E) load_edge(EI, e, E, is64, s, d);
            else       s = d = e - E;
            int pos = atomicAdd(&g_cur[d], 1);
            g_ssrc[pos] = s;
        }
    }
}

// ---------------- K3: persistent fp16 GEMM, 3-stage A pipe, B loaded once ----
// (R15 structure, scatter removed — it runs concurrently on a forked stream.)
__device__ __forceinline__ void ldsm_x4(uint32_t& r0, uint32_t& r1,
                                        uint32_t& r2, uint32_t& r3, uint32_t addr) {
    asm volatile("ldmatrix.sync.aligned.m8n8.x4.shared.b16 {%0,%1,%2,%3}, [%4];\n"
                 : "=r"(r0), "=r"(r1), "=r"(r2), "=r"(r3) : "r"(addr));
}

__device__ __forceinline__ void mma_fp16(float c[4], const uint32_t a[4],
                                         const uint32_t b[2]) {
    asm volatile(
        "mma.sync.aligned.m16n8k16.row.col.f32.f16.f16.f32 "
        "{%0,%1,%2,%3},{%4,%5,%6,%7},{%8,%9},{%0,%1,%2,%3};\n"
        : "+f"(c[0]), "+f"(c[1]), "+f"(c[2]), "+f"(c[3])
        : "r"(a[0]), "r"(a[1]), "r"(a[2]), "r"(a[3]), "r"(b[0]), "r"(b[1]));
}

__device__ __forceinline__ void cp16(uint32_t dst, const void* src, int srcsize) {
    asm volatile("cp.async.cg.shared.global [%0], [%1], 16, %2;\n"
                 :: "r"(dst), "l"(src), "r"(srcsize) : "memory");
}
__device__ __forceinline__ void cp_commit() {
    asm volatile("cp.async.commit_group;\n" ::: "memory");
}
template <int N>
__device__ __forceinline__ void cp_wait() {
    asm volatile("cp.async.wait_group %0;\n" :: "n"(N) : "memory");
}

template <int STAGES>
__global__ __launch_bounds__(256, 3)
void gemm_fp16_kernel(const float* __restrict__ att_src,
                      const float* __restrict__ att_dst) {
    extern __shared__ __align__(16) char dynsmem[];

    const int tid  = threadIdx.x;
    const int lane = tid & 31;
    const int warp = tid >> 5;
    const int wm = (warp & 3) * 32;
    const int wn = (warp >> 2) * 32;
    const int bid = blockIdx.x;
    const int n0  = (bid & 3) * GBN;        // fixed for the whole block

    const uint32_t baseA = (uint32_t)__cvta_generic_to_shared(dynsmem);
    const uint32_t baseB = baseA + STAGES * A_STAGE_B;

    const int ntiles = (NTILES - bid + GEMM_GRID - 1) / GEMM_GRID;
    const int P = 2 * ntiles;

    auto issueA = [&](int p) {
        const int T = bid + (p >> 1) * GEMM_GRID;
        const int row0 = (T >> 2) * GBM;
        const int stage = p % STAGES;
        const int kk = (p & 1) * GBK;
        #pragma unroll
        for (int j = 0; j < 4; j++) {
            int slot = tid + j * 256;
            int r  = slot >> 3;
            int cc = slot & 7;
            int gr = row0 + r;
            const void* src = &g_Ah[(size_t)min(gr, N_NODES - 1) * IN_DIM + kk + cc * 8];
            uint32_t dst = baseA + stage * A_STAGE_B + r * 128 + (cc ^ (r & 7)) * 16;
            cp16(dst, src, (gr < N_NODES) ? 16 : 0);
        }
        cp_commit();
    };

    // ---- prologue: B slab once (group 0) + first STAGES A chunks ----
    {
        #pragma unroll
        for (int j = 0; j < 4; j++) {
            int slot = tid + j * 256;        // 0..1023
            int c  = slot >> 9;              // k-chunk 0/1
            int s2 = slot & 511;
            int r  = s2 >> 3;
            int cc = s2 & 7;
            const void* src = &g_Bth[(size_t)(n0 + r) * IN_DIM + c * GBK + cc * 8];
            uint32_t dst = baseB + c * B_CHUNK_B + r * 128 + (cc ^ (r & 7)) * 16;
            cp16(dst, src, 16);
        }
        cp_commit();
    }
    #pragma unroll
    for (int p0 = 0; p0 < STAGES; p0++) issueA(p0);

    float acc[2][4][4];
    #pragma unroll
    for (int i = 0; i < 2; i++)
        #pragma unroll
        for (int j = 0; j < 4; j++)
            #pragma unroll
            for (int e = 0; e < 4; e++) acc[i][j][e] = 0.f;

    #pragma unroll 1
    for (int p = 0; p < P; p++) {
        int ahead = P - 1 - p;
        if (ahead > STAGES - 1) ahead = STAGES - 1;
        if (ahead >= 2)      cp_wait<2>();
        else if (ahead == 1) cp_wait<1>();
        else                 cp_wait<0>();
        __syncthreads();

        const uint32_t aOff = baseA + (p % STAGES) * A_STAGE_B;
        const uint32_t bOff = baseB + (p & 1) * B_CHUNK_B;
        #pragma unroll
        for (int k0 = 0; k0 < GBK; k0 += 16) {
            uint32_t a[2][4];
            #pragma unroll
            for (int i = 0; i < 2; i++) {
                int r = wm + 16 * i + (lane & 15);
                int cc = (k0 >> 3) + ((lane >> 4) & 1);
                ldsm_x4(a[i][0], a[i][1], a[i][2], a[i][3],
                        aOff + r * 128 + ((cc ^ (r & 7)) * 16));
            }
            uint32_t b[4][2];
            #pragma unroll
            for (int jj = 0; jj < 2; jj++) {
                int r = wn + jj * 16 + (lane & 7) + ((lane & 16) ? 8 : 0);
                int cc = (k0 >> 3) + ((lane >> 3) & 1);
                uint32_t r0, r1, r2, r3;
                ldsm_x4(r0, r1, r2, r3, bOff + r * 128 + ((cc ^ (r & 7)) * 16));
                b[2 * jj][0] = r0; b[2 * jj][1] = r1;
                b[2 * jj + 1][0] = r2; b[2 * jj + 1][1] = r3;
            }
            #pragma unroll
            for (int i = 0; i < 2; i++)
                #pragma unroll
                for (int j = 0; j < 4; j++)
                    mma_fp16(acc[i][j], a[i], b[j]);
        }
        __syncthreads();          // stage reads done; safe to refill this stage
        if (p + STAGES < P) issueA(p + STAGES);

        if (p & 1) {
            // ---- tile epilogue: store h (fp16) + fused per-head logits ----
            const int T = bid + (p >> 1) * GEMM_GRID;
            const int row0 = (T >> 2) * GBM;
            const int g   = lane >> 2;
            const int tig = lane & 3;
            const int head = (n0 >> 5) + (wn >> 5);

            float as_v[4][2], ad_v[4][2];
            #pragma unroll
            for (int j = 0; j < 4; j++) {
                int col = j * 8 + 2 * tig;
                as_v[j][0] = att_src[head * 32 + col];
                as_v[j][1] = att_src[head * 32 + col + 1];
                ad_v[j][0] = att_dst[head * 32 + col];
                ad_v[j][1] = att_dst[head * 32 + col + 1];
            }

            float ps[4] = {0.f, 0.f, 0.f, 0.f}, pd[4] = {0.f, 0.f, 0.f, 0.f};
            #pragma unroll
            for (int i = 0; i < 2; i++) {
                int row1 = row0 + wm + 16 * i + g;
                int row2 = row1 + 8;
                #pragma unroll
                for (int j = 0; j < 4; j++) {
                    int colg = n0 + wn + j * 8 + 2 * tig;
                    if (row1 < N_NODES)
                        *(__half2*)&g_hh[(size_t)row1 * HF + colg] =
                            __floats2half2_rn(acc[i][j][0], acc[i][j][1]);
                    if (row2 < N_NODES)
                        *(__half2*)&g_hh[(size_t)row2 * HF + colg] =
                            __floats2half2_rn(acc[i][j][2], acc[i][j][3]);
                    ps[2 * i]     += acc[i][j][0] * as_v[j][0] + acc[i][j][1] * as_v[j][1];
                    ps[2 * i + 1] += acc[i][j][2] * as_v[j][0] + acc[i][j][3] * as_v[j][1];
                    pd[2 * i]     += acc[i][j][0] * ad_v[j][0] + acc[i][j][1] * ad_v[j][1];
                    pd[2 * i + 1] += acc[i][j][2] * ad_v[j][0] + acc[i][j][3] * ad_v[j][1];
                }
            }
            #pragma unroll
            for (int s = 0; s < 4; s++) {
                ps[s] += __shfl_xor_sync(0xffffffffu, ps[s], 1);
                ps[s] += __shfl_xor_sync(0xffffffffu, ps[s], 2);
                pd[s] += __shfl_xor_sync(0xffffffffu, pd[s], 1);
                pd[s] += __shfl_xor_sync(0xffffffffu, pd[s], 2);
            }
            if (tig == 0) {
                #pragma unroll
                for (int s = 0; s < 4; s++) {
                    int row = row0 + wm + 16 * (s >> 1) + 8 * (s & 1) + g;
                    if (row < N_NODES) {
                        g_asrc[row * HEADS + head] = ps[s];
                        g_adst[row * HEADS + head] = pd[s];
                    }
                }
            }
            #pragma unroll
            for (int i = 0; i < 2; i++)
                #pragma unroll
                for (int j = 0; j < 4; j++)
                    #pragma unroll
                    for (int e2 = 0; e2 < 4; e2++) acc[i][j][e2] = 0.f;
        }
    }
}

// ---------------- K4: fused softmax + aggregation (warp per destination) ------
__global__ void agg2_kernel(const float* __restrict__ bias,
                            float* __restrict__ out) {
    int wid  = (blockIdx.x * blockDim.x + threadIdx.x) >> 5;
    int lane = threadIdx.x & 31;
    if (wid >= N_NODES) return;
    const int d = wid;
    const int beg = g_off[d], end = g_off[d + 1];
    const int hd = lane >> 2;

    float adv = (lane < HEADS) ? g_adst[d * HEADS + lane] : 0.f;
    float num[8] = {0.f, 0.f, 0.f, 0.f, 0.f, 0.f, 0.f, 0.f};
    float den = 0.f;

    auto weight = [&](int s) -> float {
        float w = 0.f;
        if (lane < HEADS) {
            float x = __ldg(&g_asrc[s * HEADS + lane]) + adv;
            x = (x > 0.f) ? x : NEG_SLOPE * x;
            w = __expf(x);
            den += w;
        }
        return w;
    };
    auto accum = [&](uint4 v, float w) {
        float wh = __shfl_sync(0xffffffffu, w, hd);
        const __half2* hp = (const __half2*)&v;
        #pragma unroll
        for (int k = 0; k < 4; k++) {
            float2 f = __half22float2(hp[k]);
            num[2 * k]     += wh * f.x;
            num[2 * k + 1] += wh * f.y;
        }
    };

    int i = beg;
    for (; i + 4 <= end; i += 4) {
        int s0 = __ldg(&g_ssrc[i]);
        int s1 = __ldg(&g_ssrc[i + 1]);
        int s2 = __ldg(&g_ssrc[i + 2]);
        int s3 = __ldg(&g_ssrc[i + 3]);
        uint4 v0 = __ldg((const uint4*)&g_hh[(size_t)s0 * HF + lane * 8]);
        uint4 v1 = __ldg((const uint4*)&g_hh[(size_t)s1 * HF + lane * 8]);
        uint4 v2 = __ldg((const uint4*)&g_hh[(size_t)s2 * HF + lane * 8]);
        uint4 v3 = __ldg((const uint4*)&g_hh[(size_t)s3 * HF + lane * 8]);
        float w0 = weight(s0);
        float w1 = weight(s1);
        float w2 = weight(s2);
        float w3 = weight(s3);
        accum(v0, w0);
        accum(v1, w1);
        accum(v2, w2);
        accum(v3, w3);
    }
    for (; i < end; i++) {
        int s0 = __ldg(&g_ssrc[i]);
        uint4 v0 = __ldg((const uint4*)&g_hh[(size_t)s0 * HF + lane * 8]);
        accum(v0, weight(s0));
    }

    float dh = __shfl_sync(0xffffffffu, den, hd);
    float inv = 1.0f / (dh + 1e-16f);
    #pragma unroll
    for (int j = 0; j < 8; j++) {
        float c = num[j] * inv;
        c += __shfl_xor_sync(0xffffffffu, c, 4);
        c += __shfl_xor_sync(0xffffffffu, c, 8);
        c += __shfl_xor_sync(0xffffffffu, c, 16);
        num[j] = c;
    }
    if (lane < 4) {
        float4 b0 = ((const float4*)bias)[lane * 2];
        float4 b1 = ((const float4*)bias)[lane * 2 + 1];
        float4 o0 = make_float4(num[0] * 0.125f + b0.x, num[1] * 0.125f + b0.y,
                                num[2] * 0.125f + b0.z, num[3] * 0.125f + b0.w);
        float4 o1 = make_float4(num[4] * 0.125f + b1.x, num[5] * 0.125f + b1.y,
                                num[6] * 0.125f + b1.z, num[7] * 0.125f + b1.w);
        ((float4*)&out[d * OUT_DIM])[lane * 2]     = o0;
        ((float4*)&out[d * OUT_DIM])[lane * 2 + 1] = o1;
    }
}

// ---------------- launch ----------------
extern "C" void kernel_launch(void* const* d_in, const int* in_sizes, int n_in,
                              void* d_out, int out_size) {
    const float* X       = (const float*)d_in[0];
    const void*  EI      = d_in[1];
    const float* W       = (const float*)d_in[2];
    const float* att_src = (const float*)d_in[3];
    const float* att_dst = (const float*)d_in[4];
    const float* bias    = (const float*)d_in[5];
    float* out = (float*)d_out;

    int E = in_sizes[1] / 2;
    int total = E + N_NODES;

    // one-time side-stream + events (host objects only; created on the first,
    // non-captured, correctness call and reused during capture)
    static cudaStream_t s2 = nullptr;
    static cudaEvent_t evFork = nullptr, evJoin = nullptr;
    static bool tried = false;
    if (!tried) {
        tried = true;
        if (cudaStreamCreateWithFlags(&s2, cudaStreamNonBlocking) != cudaSuccess) s2 = nullptr;
        if (s2) {
            if (cudaEventCreateWithFlags(&evFork, cudaEventDisableTiming) != cudaSuccess ||
                cudaEventCreateWithFlags(&evJoin, cudaEventDisableTiming) != cudaSuccess)
                s2 = nullptr;
        }
        (void)cudaGetLastError();
    }

    init_kernel<<<(N_NODES + 255) / 256, 256>>>(EI);
    prep_kernel<<<(N_NODES * IN_DIM / 4 + 255) / 256, 256>>>(X, W, EI, E);

    const int smem3 = 3 * A_STAGE_B + 2 * B_CHUNK_B;   // 65536
    const int smem2 = 2 * A_STAGE_B + 2 * B_CHUNK_B;   // 49152
    cudaError_t aerr = cudaFuncSetAttribute(
        gemm_fp16_kernel<3>, cudaFuncAttributeMaxDynamicSharedMemorySize, smem3);
    (void)cudaGetLastError();

    if (s2) {
        // fork: scan+scatter run concurrently with the GEMM
        cudaEventRecord(evFork, 0);
        cudaStreamWaitEvent(s2, evFork, 0);
        scan_kernel<<<SCAN_NB, 1024, 0, s2>>>(E);
        scatter_kernel<<<(total + 1023) / 1024, 256, 0, s2>>>(EI, E);
        cudaEventRecord(evJoin, s2);

        if (aerr == cudaSuccess)
            gemm_fp16_kernel<3><<<GEMM_GRID, 256, smem3>>>(att_src, att_dst);
        else
            gemm_fp16_kernel<2><<<GEMM_GRID, 256, smem2>>>(att_src, att_dst);

        cudaStreamWaitEvent(0, evJoin, 0);
    } else {
        // fallback: sequential
        scan_kernel<<<SCAN_NB, 1024>>>(E);
        scatter_kernel<<<(total + 1023) / 1024, 256>>>(EI, E);
        if (aerr == cudaSuccess)
            gemm_fp16_kernel<3><<<GEMM_GRID, 256, smem3>>>(att_src, att_dst);
        else
            gemm_fp16_kernel<2><<<GEMM_GRID, 256, smem2>>>(att_src, att_dst);
    }

    agg2_kernel<<<(N_NODES * 32 + 255) / 256, 256>>>(bias, out);
}